// round 2
// baseline (speedup 1.0000x reference)
#include <cuda_runtime.h>
#include <cuda_bf16.h>

// YOLO head decode: (B, 3*85, 52, 52) -> (B, 3*52*52, 85)
//   c==0: (sigmoid(v)+gx)*stride
//   c==1: (sigmoid(v)+gy)*stride
//   c==2: exp(v)*anchor_w      (stride cancels: exp(w)*(A/stride)*stride)
//   c==3: exp(v)*anchor_h
//   c>=4: sigmoid(v)
//
// HBM-bound streaming permute. Shared-memory transpose tile:
//   one block = one (b,a) plane x 104 spatial positions (2 full grid rows).
//   Load: float4-coalesced along spatial dim, transform applied inline.
//   Store: fully linear coalesced (out offset == plane*229840 + tile*8840 + idx).

#define G       52
#define GG      2704        // 52*52
#define NCH     85
#define NA      3
#define TILE    104         // 2 grid rows; 2704/104 == 26 exactly
#define NT4     26          // TILE/4
#define TPP     26          // tiles per plane
#define TPAD    105         // smem row pad: 105 mod 32 = 9, gcd(9,32)=1 -> conflict free
#define THREADS 256

__global__ __launch_bounds__(THREADS)
void yolo_decode_kernel(const float* __restrict__ x,
                        const void* __restrict__ img_raw,
                        float* __restrict__ out)
{
    __shared__ float s[NCH * TPAD];

    const int blk   = blockIdx.x;
    const int tile  = blk % TPP;
    const int plane = blk / TPP;          // b*3 + a
    const int a     = plane % NA;

    // ---- decode img_dim scalar; tolerate missing input or unknown dtype ----
    float img = 416.0f;
    if (img_raw != nullptr) {
        const int lo = *(const int*)img_raw;
        if (lo >= 1 && lo <= 1000000) {
            img = (float)lo;                              // int32 / int64 low word
        } else {
            const float f = __int_as_float(lo);
            if (f >= 1.f && f <= 1.e6f) img = f;          // float32
        }
    }
    const float stride = img * (1.f / (float)G);

    const float aw = (a == 0) ? 10.f : (a == 1) ? 16.f : 33.f;
    const float ah = (a == 0) ? 13.f : (a == 1) ? 30.f : 23.f;

    // ---- load + transform: coalesced float4 reads along spatial dim ----
    // float offset of (c,pos): plane*NCH*GG + c*GG + tile*TILE + pos   (all mult of 4)
    const int base4 = (plane * (NCH * GG) + tile * TILE) >> 2;
    const int gy0   = tile * 2;           // tile covers grid rows gy0, gy0+1
    const float4* __restrict__ in4 = (const float4*)x;

    for (int idx = threadIdx.x; idx < NCH * NT4; idx += THREADS) {
        const int c  = idx / NT4;
        const int p4 = idx - c * NT4;
        const float4 v = in4[base4 + c * (GG >> 2) + p4];
        const int pos = p4 << 2;

        float r[4] = {v.x, v.y, v.z, v.w};
        #pragma unroll
        for (int j = 0; j < 4; j++) {
            const float val = r[j];
            float o;
            if (c == 2) {
                o = __expf(val) * aw;
            } else if (c == 3) {
                o = __expf(val) * ah;
            } else {
                const float sg = 1.f / (1.f + __expf(-val));
                if (c == 0) {
                    const int p  = pos + j;
                    const int gx = (p >= G) ? (p - G) : p;
                    o = (sg + (float)gx) * stride;
                } else if (c == 1) {
                    const int gy = gy0 + ((pos + j) >= G ? 1 : 0);
                    o = (sg + (float)gy) * stride;
                } else {
                    o = sg;
                }
            }
            s[c * TPAD + pos + j] = o;
        }
    }

    __syncthreads();

    // ---- store: fully linear coalesced writes ----
    // out[((plane)*GG + tile*TILE + p)*NCH + c] with idx = p*NCH + c
    float* __restrict__ outp = out + (size_t)plane * (GG * NCH) + (size_t)tile * (TILE * NCH);
    for (int idx = threadIdx.x; idx < NCH * TILE; idx += THREADS) {
        const int p = idx / NCH;
        const int c = idx - p * NCH;
        outp[idx] = s[c * TPAD + p];
    }
}

extern "C" void kernel_launch(void* const* d_in, const int* in_sizes, int n_in,
                              void* d_out, int out_size)
{
    const float* x = (const float*)d_in[0];

    // img_dim scalar may or may not be present as a device input
    const void* img = (n_in >= 2 && in_sizes[1] >= 1) ? d_in[1] : nullptr;

    float* out = (float*)d_out;

    // Batch from x size; fall back to out_size if inconsistent.
    int B = in_sizes[0] / (NA * NCH * GG);
    if (B <= 0) B = out_size / (NA * GG * NCH);
    const int grid = B * NA * TPP;                 // 4992 blocks @ B=64

    yolo_decode_kernel<<<grid, THREADS>>>(x, img, out);
}

// round 5
// speedup vs baseline: 1.2889x; 1.2889x over previous
#include <cuda_runtime.h>
#include <cuda_bf16.h>

// YOLO head decode: (B, 3*85, 52, 52) -> (B, 3*52*52, 85)
//   c==0: (sigmoid(v)+gx)*stride
//   c==1: (sigmoid(v)+gy)*stride
//   c==2: exp(v)*anchor_w      (stride cancels: exp(w)*(A/stride)*stride)
//   c==3: exp(v)*anchor_h
//   c>=4: sigmoid(v)
//
// R5: smem laid out in the FLAT OUTPUT order s[p*85+c] (no pad, 17.68KB).
//   Load:  float4-coalesced gmem reads along spatial dim, transform inline,
//          scattered STS (4-way conflict — same degree as the padded variant had).
//   Store: pure contiguous float4 smem->gmem copy: LDS.128 + STG.128, zero
//          index math. Attacks the measured binder (issue=70.5%, alu=46.2%).

#define G       52
#define GG      2704        // 52*52
#define NCH     85
#define NA      3
#define NT4     13          // 52/4 float4s per channel row
#define NLOAD   1105        // 85*13 float4 loads per tile
#define TOUT    4420        // 52*85 floats per tile (= smem size, = out slice)
#define NOUT4   1105        // 4420/4 float4 stores per tile
#define THREADS 256

__global__ __launch_bounds__(THREADS)
void yolo_decode_kernel(const float* __restrict__ x,
                        const void* __restrict__ img_raw,
                        float* __restrict__ out)
{
    __shared__ __align__(16) float s[TOUT];

    const int tile  = blockIdx.x % G;     // grid row (gy)
    const int plane = blockIdx.x / G;     // b*3 + a
    const int a     = plane % NA;

    // ---- decode img_dim scalar; tolerate missing input or unknown dtype ----
    float img = 416.0f;
    if (img_raw != nullptr) {
        const int lo = *(const int*)img_raw;
        if (lo >= 1 && lo <= 1000000) {
            img = (float)lo;                              // int32 / int64 low word
        } else {
            const float f = __int_as_float(lo);
            if (f >= 1.f && f <= 1.e6f) img = f;          // float32
        }
    }
    const float stride = img * (1.f / (float)G);
    const float gyf    = (float)tile;

    const float aw = (a == 0) ? 10.f : (a == 1) ? 16.f : 33.f;
    const float ah = (a == 0) ? 13.f : (a == 1) ? 30.f : 23.f;

    // ---- load + transform: coalesced float4 reads along spatial dim ----
    // float4 offset of (c, p4): (plane*NCH*GG + tile*G)/4 + c*(GG/4) + p4
    const int base4 = (plane * (NCH * GG) + tile * G) >> 2;
    const float4* __restrict__ in4 = (const float4*)x;

    for (int idx = threadIdx.x; idx < NLOAD; idx += THREADS) {
        const int c  = idx / NT4;
        const int p4 = idx - c * NT4;
        const float4 v = in4[base4 + c * (GG >> 2) + p4];
        const int pos = p4 << 2;

        float r[4] = {v.x, v.y, v.z, v.w};
        #pragma unroll
        for (int j = 0; j < 4; j++) {
            const float val = r[j];
            float o;
            if (c == 2) {
                o = __expf(val) * aw;
            } else if (c == 3) {
                o = __expf(val) * ah;
            } else {
                const float sg = __fdividef(1.0f, 1.0f + __expf(-val));
                if (c == 0) {
                    o = (sg + (float)(pos + j)) * stride;   // gx = position in row
                } else if (c == 1) {
                    o = (sg + gyf) * stride;                // gy = tile
                } else {
                    o = sg;
                }
            }
            // smem in flat output order: element (p, c) at p*85 + c
            s[(pos + j) * NCH + c] = o;
        }
    }

    __syncthreads();

    // ---- store: contiguous float4 copy smem -> gmem (no index math) ----
    const float4* __restrict__ s4 = (const float4*)s;
    float4* __restrict__ out4 =
        (float4*)(out + (size_t)plane * (GG * NCH) + (size_t)tile * TOUT);

    for (int idx4 = threadIdx.x; idx4 < NOUT4; idx4 += THREADS) {
        out4[idx4] = s4[idx4];
    }
}

extern "C" void kernel_launch(void* const* d_in, const int* in_sizes, int n_in,
                              void* d_out, int out_size)
{
    const float* x = (const float*)d_in[0];

    // img_dim scalar may or may not be present as a device input
    const void* img = (n_in >= 2 && in_sizes[1] >= 1) ? d_in[1] : nullptr;

    float* out = (float*)d_out;

    int B = in_sizes[0] / (NA * NCH * GG);
    if (B <= 0) B = out_size / (NA * GG * NCH);
    const int grid = B * NA * G;                 // 9984 blocks @ B=64

    yolo_decode_kernel<<<grid, THREADS>>>(x, img, out);
}

// round 7
// speedup vs baseline: 1.3742x; 1.0662x over previous
#include <cuda_runtime.h>
#include <cuda_bf16.h>
#include <cstdint>

// YOLO head decode: (B, 3*85, 52, 52) -> (B, 3*52*52, 85)
//   c==0: (sigmoid(v)+gx)*stride
//   c==1: (sigmoid(v)+gy)*stride
//   c==2: exp(v)*anchor_w      (stride cancels)
//   c==3: exp(v)*anchor_h
//   c>=4: sigmoid(v)
//
// Attack the measured issue-bound profile (R5 ncu: issue=65.9%, alu=45.0%, dram=50.9%).
//   - Store loop DELETED: smem is in flat output order, one TMA bulk store
//     (cp.async.bulk.global.shared::cta) ships the whole 17680B tile.
//   - Main loop (channels 4..84, 95% of data) is branch-free pure sigmoid.
//   - Channels 0..3 handled by a tiny prologue (tid < 52).
//   - Division-free loop iteration (incremental c/p4 with carry).

#define G       52
#define GG      2704        // 52*52
#define GG4     676         // GG/4
#define NCH     85
#define NA      3
#define NT4     13          // 52/4 float4s per channel row
#define TOUT    4420        // 52*85 floats per tile (= smem = out slice)
#define TBYTES  17680       // TOUT*4, multiple of 16
#define THREADS 256

__device__ __forceinline__ float fsig(float v) {
    // 1/(1+exp(-v)) via fast exp + rcp; inputs ~N(0,1), no overflow risk
    return __fdividef(1.0f, 1.0f + __expf(-v));
}

__global__ __launch_bounds__(THREADS)
void yolo_decode_kernel(const float* __restrict__ x,
                        const void* __restrict__ img_raw,
                        float* __restrict__ out)
{
    __shared__ __align__(16) float s[TOUT];

    const int tid   = threadIdx.x;
    const int tile  = blockIdx.x % G;     // grid row (gy)
    const int plane = blockIdx.x / G;     // b*3 + a
    const int a     = plane % NA;

    // ---- decode img_dim scalar; tolerate missing input or unknown dtype ----
    float img = 416.0f;
    if (img_raw != nullptr) {
        const int lo = *(const int*)img_raw;
        if (lo >= 1 && lo <= 1000000) {
            img = (float)lo;                              // int32 / int64 low word
        } else {
            const float f = __int_as_float(lo);
            if (f >= 1.f && f <= 1.e6f) img = f;          // float32
        }
    }
    const float stride = img * (1.f / (float)G);
    const float gyf    = (float)tile;

    const int base4 = (plane * (NCH * GG) + tile * G) >> 2;
    const float4* __restrict__ in4 = (const float4*)x;

    // ---- prologue: special channels 0..3 (52 float4s), tid < 52 ----
    if (tid < 4 * NT4) {
        const int c  = tid / NT4;         // 0..3
        const int p4 = tid - c * NT4;
        const float4 v = in4[base4 + c * GG4 + p4];
        const int pos = p4 << 2;
        const float aw = (a == 0) ? 10.f : (a == 1) ? 16.f : 33.f;
        const float ah = (a == 0) ? 13.f : (a == 1) ? 30.f : 23.f;

        float r[4] = {v.x, v.y, v.z, v.w};
        #pragma unroll
        for (int j = 0; j < 4; j++) {
            const float val = r[j];
            float o;
            if (c == 0)      o = (fsig(val) + (float)(pos + j)) * stride;
            else if (c == 1) o = (fsig(val) + gyf) * stride;
            else if (c == 2) o = __expf(val) * aw;
            else             o = __expf(val) * ah;
            s[(pos + j) * NCH + c] = o;
        }
    }

    // ---- main loop: channels 4..84, pure sigmoid, branch-free, div-free ----
    // Flattened item i = (c-4)*13 + p4 walked with stride THREADS=256 = 19*13+9.
    {
        const int q = tid / NT4;          // one div at entry only
        int c  = 4 + q;
        int p4 = tid - q * NT4;
        while (c < NCH) {
            const float4 v = in4[base4 + c * GG4 + p4];
            float* sp = s + (p4 << 2) * NCH + c;   // element (p,c) at p*85+c
            sp[0 * NCH] = fsig(v.x);
            sp[1 * NCH] = fsig(v.y);
            sp[2 * NCH] = fsig(v.z);
            sp[3 * NCH] = fsig(v.w);
            c += 19; p4 += 9;
            if (p4 >= NT4) { p4 -= NT4; c += 1; }
        }
    }

    __syncthreads();

    // ---- store: single TMA bulk copy smem -> gmem (no store loop at all) ----
    if (tid == 0) {
        float* gptr = out + (size_t)plane * (GG * NCH) + (size_t)tile * TOUT;
        uint32_t saddr;
        asm("{ .reg .u64 t; cvta.to.shared.u64 t, %1; cvt.u32.u64 %0, t; }"
            : "=r"(saddr) : "l"(s));
        asm volatile("fence.proxy.async.shared::cta;" ::: "memory");
        asm volatile(
            "cp.async.bulk.global.shared::cta.bulk_group [%0], [%1], %2;"
            :: "l"(gptr), "r"(saddr), "r"(TBYTES) : "memory");
        asm volatile("cp.async.bulk.commit_group;" ::: "memory");
        // Wait for the bulk engine to finish READING smem before the block
        // exits (smem may be reassigned to the next resident block).
        asm volatile("cp.async.bulk.wait_group 0;" ::: "memory");
    }
}

extern "C" void kernel_launch(void* const* d_in, const int* in_sizes, int n_in,
                              void* d_out, int out_size)
{
    const float* x = (const float*)d_in[0];
    const void* img = (n_in >= 2 && in_sizes[1] >= 1) ? d_in[1] : nullptr;
    float* out = (float*)d_out;

    int B = in_sizes[0] / (NA * NCH * GG);
    if (B <= 0) B = out_size / (NA * GG * NCH);
    const int grid = B * NA * G;                 // 9984 blocks @ B=64

    yolo_decode_kernel<<<grid, THREADS>>>(x, img, out);
}

// round 10
// speedup vs baseline: 1.7510x; 1.2741x over previous
#include <cuda_runtime.h>
#include <cuda_bf16.h>
#include <cstdint>

// YOLO head decode: (B, 3*85, 52, 52) -> (B, 3*52*52, 85)
//   c==0: (sigmoid(v)+gx)*stride
//   c==1: (sigmoid(v)+gy)*stride
//   c==2: exp(v)*anchor_w      (stride cancels)
//   c==3: exp(v)*anchor_h
//   c>=4: sigmoid(v)
//
// Latency-bound fix (R7 ncu: issue=31.3%, dram=55.8%, regs=22 -> MLP~1).
//   5-slot fully-unrolled schedule: all 5 independent LDG.128s issued FIRST
//   (front-batched, MLP=5/thread), then sigmoid + STS. Slot indices are
//   RECOMPUTED in the compute phase (mulhi const-div) instead of held in
//   registers across the load window -> lower reg pressure, occupancy kept.
//   Keeps: flat-output smem layout, single cp.async.bulk store, branch-free
//   sigmoid path for channels 4..84, tiny prologue for channels 0..3.

#define G       52
#define GG      2704        // 52*52
#define GG4     676         // GG/4
#define NCH     85
#define NA      3
#define NT4     13          // 52/4 float4s per channel row
#define NMAIN   1053        // 81 sigmoid channels * 13 float4s
#define NSLOT   5           // ceil(1053/256)
#define TOUT    4420        // 52*85 floats per tile (= smem = out slice)
#define TBYTES  17680       // TOUT*4, multiple of 16
#define THREADS 256

__device__ __forceinline__ float fsig(float v) {
    // 1/(1+exp(-v)) via fast exp + rcp; inputs ~N(0,1), no overflow risk
    return __fdividef(1.0f, 1.0f + __expf(-v));
}

__global__ __launch_bounds__(THREADS)
void yolo_decode_kernel(const float* __restrict__ x,
                        const void* __restrict__ img_raw,
                        float* __restrict__ out)
{
    __shared__ __align__(16) float s[TOUT];

    const int tid   = threadIdx.x;
    const int tile  = blockIdx.x % G;     // grid row (gy)
    const int plane = blockIdx.x / G;     // b*3 + a
    const int a     = plane % NA;

    // ---- decode img_dim scalar; tolerate missing input or unknown dtype ----
    float img = 416.0f;
    if (img_raw != nullptr) {
        const int lo = *(const int*)img_raw;
        if (lo >= 1 && lo <= 1000000) {
            img = (float)lo;                              // int32 / int64 low word
        } else {
            const float f = __int_as_float(lo);
            if (f >= 1.f && f <= 1.e6f) img = f;          // float32
        }
    }
    const float stride = img * (1.f / (float)G);
    const float gyf    = (float)tile;

    const int base4 = (plane * (NCH * GG) + tile * G) >> 2;
    const float4* __restrict__ in4 = (const float4*)x;

    // ================= FRONT-BATCHED LOADS (max MLP) =================

    // prologue load: special channels 0..3 (52 float4s), tid < 52
    float4 pv;
    const bool has_pro = (tid < 4 * NT4);
    const int pc  = tid / NT4;            // 0..3 (only meaningful if has_pro)
    const int pp4 = tid - pc * NT4;
    if (has_pro) {
        pv = in4[base4 + pc * GG4 + pp4];
    }

    // main loads: channels 4..84, 5 predicated slots, all issued back-to-back
    float4 v[NSLOT];
    #pragma unroll
    for (int k = 0; k < NSLOT; k++) {
        const int i = tid + k * THREADS;
        if (i < NMAIN) {
            const int q = i / NT4;        // const-div -> mulhi, cheap
            v[k] = in4[base4 + (4 + q) * GG4 + (i - q * NT4)];
        }
    }

    // ================= COMPUTE + STS =================

    if (has_pro) {
        const int pos = pp4 << 2;
        const float aw = (a == 0) ? 10.f : (a == 1) ? 16.f : 33.f;
        const float ah = (a == 0) ? 13.f : (a == 1) ? 30.f : 23.f;
        float r[4] = {pv.x, pv.y, pv.z, pv.w};
        #pragma unroll
        for (int j = 0; j < 4; j++) {
            const float val = r[j];
            float o;
            if (pc == 0)      o = (fsig(val) + (float)(pos + j)) * stride;
            else if (pc == 1) o = (fsig(val) + gyf) * stride;
            else if (pc == 2) o = __expf(val) * aw;
            else              o = __expf(val) * ah;
            s[(pos + j) * NCH + pc] = o;
        }
    }

    #pragma unroll
    for (int k = 0; k < NSLOT; k++) {
        const int i = tid + k * THREADS;
        if (i < NMAIN) {
            const int q  = i / NT4;       // recomputed: cheaper than 2 live regs
            const int c  = 4 + q;
            const int p4 = i - q * NT4;
            float* sp = s + (p4 << 2) * NCH + c;   // (p,c) at p*85+c
            sp[0 * NCH] = fsig(v[k].x);
            sp[1 * NCH] = fsig(v[k].y);
            sp[2 * NCH] = fsig(v[k].z);
            sp[3 * NCH] = fsig(v[k].w);
        }
    }

    __syncthreads();

    // ---- store: single TMA bulk copy smem -> gmem (no store loop) ----
    if (tid == 0) {
        float* gptr = out + (size_t)plane * (GG * NCH) + (size_t)tile * TOUT;
        uint32_t saddr;
        asm("{ .reg .u64 t; cvta.to.shared.u64 t, %1; cvt.u32.u64 %0, t; }"
            : "=r"(saddr) : "l"(s));
        asm volatile("fence.proxy.async.shared::cta;" ::: "memory");
        asm volatile(
            "cp.async.bulk.global.shared::cta.bulk_group [%0], [%1], %2;"
            :: "l"(gptr), "r"(saddr), "r"(TBYTES) : "memory");
        asm volatile("cp.async.bulk.commit_group;" ::: "memory");
        // Ensure the bulk engine has finished READING smem before block exit.
        asm volatile("cp.async.bulk.wait_group 0;" ::: "memory");
    }
}

extern "C" void kernel_launch(void* const* d_in, const int* in_sizes, int n_in,
                              void* d_out, int out_size)
{
    const float* x = (const float*)d_in[0];
    const void* img = (n_in >= 2 && in_sizes[1] >= 1) ? d_in[1] : nullptr;
    float* out = (float*)d_out;

    int B = in_sizes[0] / (NA * NCH * GG);
    if (B <= 0) B = out_size / (NA * GG * NCH);
    const int grid = B * NA * G;                 // 9984 blocks @ B=64

    yolo_decode_kernel<<<grid, THREADS>>>(x, img, out);
}